// round 5
// baseline (speedup 1.0000x reference)
#include <cuda_runtime.h>
#include <math.h>
#include <mma.h>
using namespace nvcuda;

#define BB 128
#define SS 50
#define DD 128
#define NNODE 40000
#define SAMP 12
#define NNEI 8
#define LEAKC 0.2f
#define NSCORE 39999

// ---------------- scratch (device globals; no allocation) ----------------
__device__ float g_h[BB*SS*DD];
__device__ float g_hf1[BB*SS*DD];
__device__ float g_hf2[BB*SS*DD];
__device__ float g_x[BB*SS*DD];
__device__ float g_mirror[BB*SS*DD];
__device__ float g_xnew[BB*SS*DD];
__device__ float g_xdot[BB*SS*DD];
__device__ float g_sess[BB*DD];
__device__ float g_out0[BB*SS*DD];
__device__ float g_out1[BB*600*DD];
__device__ float g_hglob[BB*SS*DD];
__device__ float g_hs[BB*DD];
__device__ float g_hlocal[BB*DD];
__device__ float g_c2[BB*DD];
__device__ float g_beta[BB*SS];
__device__ float g_zg[BB*DD];
__device__ float g_zhT[DD*BB];
__device__ float g_partial[BB*SS];
__device__ float g_cat[BB*600*2*DD];    // [rows][256] concat buffer
__device__ float g_logits[BB*7200];     // per-sample attention logits

__device__ __forceinline__ float sigm(float x){ return 1.0f/(1.0f+expf(-x)); }

// ---------------- k_pool: h, hf1, hf2 ----------------
__global__ void k_pool(const int* __restrict__ inputs,
                       const int* __restrict__ as0, const int* __restrict__ as1,
                       const int* __restrict__ ssl0, const int* __restrict__ ssl1,
                       const float* __restrict__ emb){
  int blk = blockIdx.x; int tid = threadIdx.x;
  int node = inputs[blk];
  g_h[blk*DD+tid] = emb[node*DD+tid];
  float p1=0.f, p2=0.f;
  const int* L1[2] = {as0, as1};
  const int* L2[2] = {ssl0, ssl1};
  #pragma unroll
  for(int l=0;l<2;l++){
    float s=0.f,c=0.f;
    #pragma unroll
    for(int n=0;n<NNEI;n++){ int id=L1[l][blk*NNEI+n]; if(id!=0){ s+=emb[id*DD+tid]; c+=1.f; } }
    p1 += s/(c+1e-8f);
    s=0.f;c=0.f;
    #pragma unroll
    for(int n=0;n<NNEI;n++){ int id=L2[l][blk*NNEI+n]; if(id!=0){ s+=emb[id*DD+tid]; c+=1.f; } }
    p2 += s/(c+1e-8f);
  }
  g_hf1[blk*DD+tid] = p1*0.5f;
  g_hf2[blk*DD+tid] = p2*0.5f;
}

// ---------------- k_attr ----------------
__global__ void k_attr(const float* __restrict__ attr_w){
  int blk=blockIdx.x, tid=threadIdx.x;
  __shared__ __align__(16) float hr[DD], fr[DD];
  hr[tid]=g_h[blk*DD+tid]; fr[tid]=g_hf1[blk*DD+tid];
  __syncthreads();
  const float* wt = attr_w + tid;
  float acc=0.f;
  #pragma unroll 8
  for(int k=0;k<DD;k+=4){
    float4 h4=*(const float4*)&hr[k];
    acc=fmaf(h4.x,wt[(k  )*DD],acc); acc=fmaf(h4.y,wt[(k+1)*DD],acc);
    acc=fmaf(h4.z,wt[(k+2)*DD],acc); acc=fmaf(h4.w,wt[(k+3)*DD],acc);
  }
  #pragma unroll 8
  for(int k=0;k<DD;k+=4){
    float4 f4=*(const float4*)&fr[k];
    acc=fmaf(f4.x,wt[(DD+k  )*DD],acc); acc=fmaf(f4.y,wt[(DD+k+1)*DD],acc);
    acc=fmaf(f4.z,wt[(DD+k+2)*DD],acc); acc=fmaf(f4.w,wt[(DD+k+3)*DD],acc);
  }
  float g=sigm(acc);
  float hf = g*hr[tid] + (1.f-g)*fr[tid];
  g_x[blk*DD+tid]=hr[tid];
  g_mirror[blk*DD+tid]=hf;
}

// ---------------- k_sess ----------------
__global__ void k_sess(const int* __restrict__ inputs, const int* __restrict__ item,
                       const float* __restrict__ emb){
  int b=blockIdx.x, tid=threadIdx.x;
  float acc=0.f, cnt=0.f;
  for(int s=0;s<SS;s++){
    int inp=inputs[b*SS+s];
    if(inp!=0){ acc += emb[item[b*SS+s]*DD+tid]; cnt+=1.f; }
  }
  g_sess[b*DD+tid]=acc/cnt;
}

// ---------------- k_att_tc: TF32 tensor-core W1 GEMM + fused logit epilogue ----------------
// Per CTA: 64 sample-rows x 128 cols.  A[r][d] = src[ci(r)][d],  B[d][c] = sess[b][d]*w1[d][c].
// logits[row] = sum_c leaky(A@B + nw*w1_last[c]) * w2[c]
__global__ void __launch_bounds__(128) k_att_tc(
    const int* __restrict__ inputs, const int* __restrict__ adj_all,
    const float* __restrict__ num,
    const float* __restrict__ src,
    const float* __restrict__ w1, const float* __restrict__ w2,
    float* __restrict__ logits, int rowsPerB, int mode)
{
  const int LDA = 36;   // As stride (x4B = 144B, mult of 16)
  const int LDB = 132;  // Bs/Cs stride (x4B = 528B, mult of 16)
  int b = blockIdx.y;
  int row0 = blockIdx.x*64;
  int tid = threadIdx.x, warp = tid>>5;

  __shared__ float sess_s[DD];
  __shared__ float w1last_s[DD];
  __shared__ float w2_s[DD];
  __shared__ float nw_s[64];
  __shared__ int   ci_s[64];
  __shared__ __align__(16) float sbuf[64*36 + 32*132];  // As | Bs ; Cs aliases from 0
  float* As = sbuf;
  float* Bs = sbuf + 64*LDA;
  float* Cs = sbuf;             // 64 x 132 = 8448 <= 6528? no: reuse needs 8448
  // NOTE: Cs needs 64*132=8448 floats; sbuf is 64*36+32*132=6528. Use separate Cs tail trick:
  // we instead allocate sbuf large enough below.
  (void)Cs;

  // row metadata
  sess_s[tid]   = g_sess[b*DD+tid];
  w1last_s[tid] = w1[DD*DD+tid];
  w2_s[tid]     = w2[tid];
  if(tid<64){
    int r = row0 + tid;
    int rr = (r < rowsPerB) ? r : 0;
    int ci; float nw;
    if(mode==0){
      int i = rr/SAMP, s = rr - i*SAMP;
      int node = inputs[b*SS+i];
      ci = adj_all[node*SAMP+s]; nw = num[node*SAMP+s];
    } else if(mode==1){
      int gi = rr/SAMP, s = rr - gi*SAMP;
      int pi = gi/SAMP, ps = gi - pi*SAMP;
      int node = adj_all[inputs[b*SS+pi]*SAMP+ps];
      ci = adj_all[node*SAMP+s]; nw = num[node*SAMP+s];
    } else {
      int i = rr/SAMP, s = rr - i*SAMP;
      int node = inputs[b*SS+i];
      nw = num[node*SAMP+s];
      ci = b*600 + rr;
    }
    ci_s[tid]=ci; nw_s[tid]=nw;
  }
  __syncthreads();

  wmma::fragment<wmma::accumulator,16,16,8,float> acc[8];
  #pragma unroll
  for(int n=0;n<8;n++) wmma::fill_fragment(acc[n], 0.0f);

  int rA   = tid>>1;  int halfA = tid&1;     // A staging: row, 16-col half
  int kkB  = tid>>2;  int qB    = tid&3;     // B staging: k-row, 32-col quarter

  for(int k0=0;k0<DD;k0+=32){
    // stage A chunk [64][32]
    {
      const float* ap = src + (long long)ci_s[rA]*DD + k0 + halfA*16;
      float* as = As + rA*LDA + halfA*16;
      #pragma unroll
      for(int j=0;j<4;j++){
        float4 v = *(const float4*)&ap[j*4];
        v.x=wmma::__float_to_tf32(v.x); v.y=wmma::__float_to_tf32(v.y);
        v.z=wmma::__float_to_tf32(v.z); v.w=wmma::__float_to_tf32(v.w);
        *(float4*)&as[j*4]=v;
      }
    }
    // stage B chunk [32][128]: B[kk][c] = sess[k0+kk]*w1[k0+kk][c]
    {
      float sv = sess_s[k0+kkB];
      const float* bp = w1 + (long long)(k0+kkB)*DD + qB*32;
      float* bs = Bs + kkB*LDB + qB*32;
      #pragma unroll
      for(int j=0;j<8;j++){
        float4 v = *(const float4*)&bp[j*4];
        v.x=wmma::__float_to_tf32(v.x*sv); v.y=wmma::__float_to_tf32(v.y*sv);
        v.z=wmma::__float_to_tf32(v.z*sv); v.w=wmma::__float_to_tf32(v.w*sv);
        *(float4*)&bs[j*4]=v;
      }
    }
    __syncthreads();
    #pragma unroll
    for(int kk0=0;kk0<32;kk0+=8){
      wmma::fragment<wmma::matrix_a,16,16,8,wmma::precision::tf32,wmma::row_major> afrag;
      wmma::load_matrix_sync(afrag, As + (warp*16)*LDA + kk0, LDA);
      #pragma unroll
      for(int n=0;n<8;n++){
        wmma::fragment<wmma::matrix_b,16,16,8,wmma::precision::tf32,wmma::row_major> bfrag;
        wmma::load_matrix_sync(bfrag, Bs + kk0*LDB + n*16, LDB);
        wmma::mma_sync(acc[n], afrag, bfrag, acc[n]);
      }
    }
    __syncthreads();
  }

  // epilogue: store C to smem (reuse sbuf; need 64*132=8448 floats, sbuf has 6528 -> use Bs area too: total fits? 6528<8448)
  // To keep it safe, store per-warp 16-row slab into As-region sequentially is racy; instead use a dedicated layout:
  // we store C with stride LDB into the union starting at sbuf; 8448 floats needed. sbuf is declared 6528.
  // -> declare bigger buffer instead (see sbuf2 below).
  __shared__ __align__(16) float sbuf2[64*132 - (64*36 + 32*132) > 0 ? 64*132 - (64*36 + 32*132) : 1];
  // sbuf followed by sbuf2 may not be contiguous; so store C into (sbuf reinterpreted) only if fits.
  // Safe approach: per-warp staging buffer [16][132] x 4 warps = 64*132 floats... same size.
  // Final approach: write C slabs through As/Bs region is insufficient; use direct fragment store to global? Too slow.
  // => use cooperative row-pair reduction directly from a 16-row staging per warp:
  __shared__ __align__(16) float Cw[4][16*132/4];  // 4 warps x 16 rows x 33 floats? NOT enough either.
  // ---- fallback implemented below: each warp stores its 16x128 slab into its quarter of a 64x33?? ----
  // (see k_att_tc_v2 actually used)
}

// The staging-size arithmetic above got unwieldy; the actually-used kernel:
// same GEMM, but epilogue stores each warp's 16x128 slab into a 16x132 buffer
// per warp (4 warps x 16 x 132 x 4B = 33.8KB) -- allocated as one array.
__global__ void __launch_bounds__(128) k_att_tc2(
    const int* __restrict__ inputs, const int* __restrict__ adj_all,
    const float* __restrict__ num,
    const float* __restrict__ src,
    const float* __restrict__ w1, const float* __restrict__ w2,
    float* __restrict__ logits, int rowsPerB, int mode)
{
  const int LDA = 36;
  const int LDB = 132;
  int b = blockIdx.y;
  int row0 = blockIdx.x*64;
  int tid = threadIdx.x, warp = tid>>5;

  __shared__ float sess_s[DD];
  __shared__ float w1last_s[DD];
  __shared__ float w2_s[DD];
  __shared__ float nw_s[64];
  __shared__ int   ci_s[64];
  __shared__ __align__(16) float Cbuf[64*LDB];            // 33.8 KB (also holds As/Bs during GEMM)
  float* As = Cbuf;                 // 64*36 = 2304
  float* Bs = Cbuf + 64*LDA;        // 32*132 = 4224  (total 6528 <= 8448 OK)

  sess_s[tid]   = g_sess[b*DD+tid];
  w1last_s[tid] = w1[DD*DD+tid];
  w2_s[tid]     = w2[tid];
  if(tid<64){
    int r = row0 + tid;
    int rr = (r < rowsPerB) ? r : 0;
    int ci; float nw;
    if(mode==0){
      int i = rr/SAMP, s = rr - i*SAMP;
      int node = inputs[b*SS+i];
      ci = adj_all[node*SAMP+s]; nw = num[node*SAMP+s];
    } else if(mode==1){
      int gi = rr/SAMP, s = rr - gi*SAMP;
      int pi = gi/SAMP, ps = gi - pi*SAMP;
      int node = adj_all[inputs[b*SS+pi]*SAMP+ps];
      ci = adj_all[node*SAMP+s]; nw = num[node*SAMP+s];
    } else {
      int i = rr/SAMP, s = rr - i*SAMP;
      int node = inputs[b*SS+i];
      nw = num[node*SAMP+s];
      ci = b*600 + rr;
    }
    ci_s[tid]=ci; nw_s[tid]=nw;
  }
  __syncthreads();

  wmma::fragment<wmma::accumulator,16,16,8,float> acc[8];
  #pragma unroll
  for(int n=0;n<8;n++) wmma::fill_fragment(acc[n], 0.0f);

  int rA   = tid>>1;  int halfA = tid&1;
  int kkB  = tid>>2;  int qB    = tid&3;

  for(int k0=0;k0<DD;k0+=32){
    {
      const float* ap = src + (long long)ci_s[rA]*DD + k0 + halfA*16;
      float* as = As + rA*LDA + halfA*16;
      #pragma unroll
      for(int j=0;j<4;j++){
        float4 v = *(const float4*)&ap[j*4];
        v.x=wmma::__float_to_tf32(v.x); v.y=wmma::__float_to_tf32(v.y);
        v.z=wmma::__float_to_tf32(v.z); v.w=wmma::__float_to_tf32(v.w);
        *(float4*)&as[j*4]=v;
      }
    }
    {
      float sv = sess_s[k0+kkB];
      const float* bp = w1 + (long long)(k0+kkB)*DD + qB*32;
      float* bs = Bs + kkB*LDB + qB*32;
      #pragma unroll
      for(int j=0;j<8;j++){
        float4 v = *(const float4*)&bp[j*4];
        v.x=wmma::__float_to_tf32(v.x*sv); v.y=wmma::__float_to_tf32(v.y*sv);
        v.z=wmma::__float_to_tf32(v.z*sv); v.w=wmma::__float_to_tf32(v.w*sv);
        *(float4*)&bs[j*4]=v;
      }
    }
    __syncthreads();
    #pragma unroll
    for(int kk0=0;kk0<32;kk0+=8){
      wmma::fragment<wmma::matrix_a,16,16,8,wmma::precision::tf32,wmma::row_major> afrag;
      wmma::load_matrix_sync(afrag, As + (warp*16)*LDA + kk0, LDA);
      #pragma unroll
      for(int n=0;n<8;n++){
        wmma::fragment<wmma::matrix_b,16,16,8,wmma::precision::tf32,wmma::row_major> bfrag;
        wmma::load_matrix_sync(bfrag, Bs + kk0*LDB + n*16, LDB);
        wmma::mma_sync(acc[n], afrag, bfrag, acc[n]);
      }
    }
    __syncthreads();
  }

  // store C (64x128) into Cbuf with stride LDB
  #pragma unroll
  for(int n=0;n<8;n++)
    wmma::store_matrix_sync(Cbuf + (warp*16)*LDB + n*16, acc[n], LDB, wmma::mem_row_major);
  __syncthreads();

  // logit epilogue: 2 threads per row
  {
    int r = tid>>1, half = tid&1;
    const float* crow = Cbuf + r*LDB + half*64;
    const float* wl   = w1last_s + half*64;
    const float* w2p  = w2_s + half*64;
    float nw = nw_s[r];
    float v = 0.f;
    #pragma unroll 4
    for(int c=0;c<64;c+=4){
      float4 q = *(const float4*)&crow[c];
      float4 l = *(const float4*)&wl[c];
      float4 w = *(const float4*)&w2p[c];
      float t;
      t = q.x + nw*l.x; t = (t>0.f)?t:(LEAKC*t); v = fmaf(t,w.x,v);
      t = q.y + nw*l.y; t = (t>0.f)?t:(LEAKC*t); v = fmaf(t,w.y,v);
      t = q.z + nw*l.z; t = (t>0.f)?t:(LEAKC*t); v = fmaf(t,w.z,v);
      t = q.w + nw*l.w; t = (t>0.f)?t:(LEAKC*t); v = fmaf(t,w.w,v);
    }
    v += __shfl_xor_sync(0xffffffffu, v, 1);
    int rg = row0 + r;
    if(half==0 && rg<rowsPerB) logits[(long long)b*rowsPerB + rg] = v;
  }
}

// ---------------- k_soft_agg: softmax over 12 logits, agg, write cat row ----------------
__global__ void __launch_bounds__(32) k_soft_agg(
    const int* __restrict__ inputs, const int* __restrict__ adj_all,
    const float* __restrict__ svsrc, const float* __restrict__ nvsrc,
    const float* __restrict__ logits, int N, int mode)
{
  int blk=blockIdx.x; int b=blk/N; int i=blk-b*N; int tid=threadIdx.x;
  __shared__ int   ci_s[SAMP];
  __shared__ float lg_s[SAMP];
  int svi;
  if(mode==0){
    int node = inputs[b*SS+i]; svi = node;
    if(tid<SAMP) ci_s[tid] = adj_all[node*SAMP+tid];
  } else if(mode==1){
    int pi=i/SAMP, ps=i-pi*SAMP;
    int node = adj_all[inputs[b*SS+pi]*SAMP+ps]; svi = node;
    if(tid<SAMP) ci_s[tid] = adj_all[node*SAMP+tid];
  } else {
    svi = b*SS+i;
    if(tid<SAMP) ci_s[tid] = b*600 + i*SAMP + tid;
  }
  if(tid<SAMP) lg_s[tid] = logits[(long long)b*(N*SAMP) + i*SAMP + tid];
  __syncwarp();
  float lg[SAMP];
  #pragma unroll
  for(int s=0;s<SAMP;s++) lg[s]=lg_s[s];
  float m=-1e30f;
  #pragma unroll
  for(int s=0;s<SAMP;s++) m=fmaxf(m,lg[s]);
  float alpha[SAMP]; float den=0.f;
  #pragma unroll
  for(int s=0;s<SAMP;s++){ alpha[s]=expf(lg[s]-m); den+=alpha[s]; }
  float inv=1.f/den;
  // sv + agg (4 cols/thread via float4)
  float4 sv4 = ((const float4*)&svsrc[(long long)svi*DD])[tid];
  float a0=0.f,a1=0.f,a2=0.f,a3=0.f;
  #pragma unroll
  for(int s=0;s<SAMP;s++){
    float4 nv4 = ((const float4*)&nvsrc[(long long)ci_s[s]*DD])[tid];
    float al = alpha[s];
    a0=fmaf(al,nv4.x,a0); a1=fmaf(al,nv4.y,a1); a2=fmaf(al,nv4.z,a2); a3=fmaf(al,nv4.w,a3);
  }
  float* crow = &g_cat[(long long)blk*2*DD];
  ((float4*)crow)[tid] = sv4;
  float4 ag; ag.x=a0*inv; ag.y=a1*inv; ag.z=a2*inv; ag.w=a3*inv;
  ((float4*)(crow+DD))[tid] = ag;
}

// ---------------- k_gemm3: out = tanh(cat @ W3), tiled 32 rows x 128 cols ----------------
__global__ void __launch_bounds__(128) k_gemm3(const float* __restrict__ w3,
                                               float* __restrict__ out){
  int row0 = blockIdx.x*32; int tid=threadIdx.x;
  int c = tid;
  __shared__ __align__(16) float As[16][32];
  float acc[32];
  #pragma unroll
  for(int r=0;r<32;r++) acc[r]=0.f;
  int rld = tid & 31;
  int kq  = tid >> 5;
  for(int k0=0;k0<2*DD;k0+=16){
    float4 av = *(const float4*)&g_cat[(long long)(row0+rld)*2*DD + k0 + kq*4];
    As[kq*4+0][rld]=av.x; As[kq*4+1][rld]=av.y; As[kq*4+2][rld]=av.z; As[kq*4+3][rld]=av.w;
    __syncthreads();
    const float* w3c = w3 + (long long)k0*DD + c;
    #pragma unroll 4
    for(int k=0;k<16;k++){
      float bk = w3c[k*DD];
      #pragma unroll
      for(int r4=0;r4<8;r4++){
        float4 a = *(const float4*)&As[k][r4*4];
        acc[r4*4+0]=fmaf(a.x,bk,acc[r4*4+0]);
        acc[r4*4+1]=fmaf(a.y,bk,acc[r4*4+1]);
        acc[r4*4+2]=fmaf(a.z,bk,acc[r4*4+2]);
        acc[r4*4+3]=fmaf(a.w,bk,acc[r4*4+3]);
      }
    }
    __syncthreads();
  }
  #pragma unroll
  for(int r=0;r<32;r++)
    out[(long long)(row0+r)*DD + c] = tanhf(acc[r]);
}

// ---------------- k_attx ----------------
__global__ void k_attx(const int* __restrict__ adj, const float* __restrict__ a_local){
  int b=blockIdx.x; int tid=threadIdx.x;  // 256 threads
  __shared__ __align__(16) float xs[SS][DD+4];
  __shared__ __align__(16) float al_s[4][DD];
  __shared__ float att[SS][SS+2];
  for(int idx=tid; idx<SS*DD; idx+=256){
    int i=idx>>7, d=idx&127;
    xs[i][d]=g_x[(b*SS+i)*DD+d];
  }
  for(int idx=tid; idx<4*DD; idx+=256)
    al_s[idx>>7][idx&127]=a_local[idx];
  __syncthreads();
  for(int p=tid;p<SS*SS;p+=256){
    int i=p/SS, j=p-i*SS;
    int k=adj[b*SS*SS+p];
    float e=-9e15f;
    if(k>=1 && k<=4){
      const float* al = al_s[k-1];
      float ds=0.f;
      #pragma unroll 8
      for(int d=0;d<DD;d+=4){
        float4 xi=*(const float4*)&xs[i][d];
        float4 xj=*(const float4*)&xs[j][d];
        float4 av=*(const float4*)&al[d];
        ds += xi.x*xj.x*av.x + xi.y*xj.y*av.y + xi.z*xj.z*av.z + xi.w*xj.w*av.w;
      }
      e = (ds>0.f)?ds:(LEAKC*ds);
    }
    att[i][j]=e;
  }
  __syncthreads();
  if(tid<SS){
    float m=-1e30f;
    for(int j=0;j<SS;j++) m=fmaxf(m,att[tid][j]);
    float den=0.f;
    for(int j=0;j<SS;j++){ float e=expf(att[tid][j]-m); att[tid][j]=e; den+=e; }
    float inv=1.f/den;
    for(int j=0;j<SS;j++) att[tid][j]*=inv;
  }
  __syncthreads();
  for(int q=tid;q<SS*DD;q+=256){
    int i=q>>7, d=q&127;
    float acc=0.f;
    for(int j=0;j<SS;j++) acc += att[i][j]*xs[j][d];
    g_xnew[(b*SS+i)*DD+d]=acc;
  }
}

// ---------------- k_gate ----------------
__global__ void k_gate(const float* __restrict__ w1, const float* __restrict__ w2){
  int blk=blockIdx.x, tid=threadIdx.x;
  __shared__ __align__(16) float xn[DD], mr[DD];
  xn[tid]=g_xnew[blk*DD+tid]; mr[tid]=g_mirror[blk*DD+tid];
  __syncthreads();
  const float* w1t=w1+tid; const float* w2t=w2+tid;
  float acc=0.f;
  #pragma unroll 8
  for(int k=0;k<DD;k+=4){
    float4 x4=*(const float4*)&xn[k];
    float4 m4=*(const float4*)&mr[k];
    acc=fmaf(x4.x,w1t[(k  )*DD],acc); acc=fmaf(m4.x,w2t[(k  )*DD],acc);
    acc=fmaf(x4.y,w1t[(k+1)*DD],acc); acc=fmaf(m4.y,w2t[(k+1)*DD],acc);
    acc=fmaf(x4.z,w1t[(k+2)*DD],acc); acc=fmaf(m4.z,w2t[(k+2)*DD],acc);
    acc=fmaf(x4.w,w1t[(k+3)*DD],acc); acc=fmaf(m4.w,w2t[(k+3)*DD],acc);
  }
  float gm=sigm(acc);
  float xv=xn[tid], mv=mr[tid];
  g_x[blk*DD+tid]     = gm*xv + (1.f-gm)*mv;
  g_mirror[blk*DD+tid]= gm*mv + (1.f-gm)*xv;
}

// ---------------- k_highway ----------------
__global__ void k_highway(const float* __restrict__ hw){
  int blk=blockIdx.x, tid=threadIdx.x;
  __shared__ __align__(16) float hr[DD], xr[DD];
  hr[tid]=g_h[blk*DD+tid]; xr[tid]=g_x[blk*DD+tid];
  __syncthreads();
  const float* wt=hw+tid;
  float acc=0.f;
  #pragma unroll 8
  for(int k=0;k<DD;k+=4){
    float4 h4=*(const float4*)&hr[k];
    float4 x4=*(const float4*)&xr[k];
    acc=fmaf(h4.x,wt[(k  )*DD],acc); acc=fmaf(x4.x,wt[(DD+k  )*DD],acc);
    acc=fmaf(h4.y,wt[(k+1)*DD],acc); acc=fmaf(x4.y,wt[(DD+k+1)*DD],acc);
    acc=fmaf(h4.z,wt[(k+2)*DD],acc); acc=fmaf(x4.z,wt[(DD+k+2)*DD],acc);
    acc=fmaf(h4.w,wt[(k+3)*DD],acc); acc=fmaf(x4.w,wt[(DD+k+3)*DD],acc);
  }
  float g=sigm(acc);
  float xd=g*hr[tid]+(1.f-g)*xr[tid];
  g_xdot[blk*DD+tid]=xd;
  int s=blk%SS;
  if(s==SS-1) g_hlocal[(blk/SS)*DD+tid]=xd;
}

// ---------------- k_hs ----------------
__global__ void k_hs(const int* __restrict__ inputs){
  int b=blockIdx.x, tid=threadIdx.x;
  float acc=0.f, cnt=0.f;
  for(int s=0;s<SS;s++){
    if(inputs[b*SS+s]!=0){ acc += g_hglob[(b*SS+s)*DD+tid]; cnt+=1.f; }
  }
  g_hs[b*DD+tid]=acc/cnt;
}

// ---------------- k_c2 ----------------
__global__ void k_c2(const float* __restrict__ glu2, const float* __restrict__ glu4,
                     const float* __restrict__ glu4b){
  int b=blockIdx.x, tid=threadIdx.x;
  __shared__ __align__(16) float hsr[DD], hlr[DD];
  hsr[tid]=g_hs[b*DD+tid]; hlr[tid]=g_hlocal[b*DD+tid];
  __syncthreads();
  float acc=glu4b[tid];
  const float* w2t=glu2+tid; const float* w4t=glu4+tid;
  #pragma unroll 8
  for(int k=0;k<DD;k+=4){
    float4 s4=*(const float4*)&hsr[k];
    float4 l4=*(const float4*)&hlr[k];
    acc=fmaf(s4.x,w2t[(k  )*DD],acc); acc=fmaf(l4.x,w4t[(k  )*DD],acc);
    acc=fmaf(s4.y,w2t[(k+1)*DD],acc); acc=fmaf(l4.y,w4t[(k+1)*DD],acc);
    acc=fmaf(s4.z,w2t[(k+2)*DD],acc); acc=fmaf(l4.z,w4t[(k+2)*DD],acc);
    acc=fmaf(s4.w,w2t[(k+3)*DD],acc); acc=fmaf(l4.w,w4t[(k+3)*DD],acc);
  }
  g_c2[b*DD+tid]=acc;
}

// ---------------- k_beta ----------------
__global__ void k_beta(const int* __restrict__ inputs, const float* __restrict__ pos,
                       const float* __restrict__ glu1, const float* __restrict__ ws){
  int blk=blockIdx.x, tid=threadIdx.x;
  int s=blk%SS, b=blk/SS;
  __shared__ __align__(16) float hp[DD];
  __shared__ float red[DD];
  hp[tid]=g_xdot[blk*DD+tid] + pos[s*DD+tid];
  __syncthreads();
  const float* wt=glu1+tid;
  float acc=0.f;
  #pragma unroll 8
  for(int k=0;k<DD;k+=4){
    float4 h4=*(const float4*)&hp[k];
    acc=fmaf(h4.x,wt[(k  )*DD],acc); acc=fmaf(h4.y,wt[(k+1)*DD],acc);
    acc=fmaf(h4.z,wt[(k+2)*DD],acc); acc=fmaf(h4.w,wt[(k+3)*DD],acc);
  }
  float nh=sigm(acc + g_c2[b*DD+tid]);
  red[tid]=nh*ws[tid];
  __syncthreads();
  for(int off=64;off>0;off>>=1){ if(tid<off) red[tid]+=red[tid+off]; __syncthreads(); }
  if(tid==0){
    float mi=(inputs[blk]!=0)?1.f:0.f;
    g_beta[blk]=red[0]*mi;
  }
}

// ---------------- k_zg ----------------
__global__ void k_zg(const float* __restrict__ pos){
  int b=blockIdx.x, tid=threadIdx.x;
  float acc=0.f;
  for(int s=0;s<SS;s++)
    acc += g_beta[b*SS+s]*(g_xdot[(b*SS+s)*DD+tid]+pos[s*DD+tid]);
  g_zg[b*DD+tid]=acc;
}

// ---------------- k_zh ----------------
__global__ void k_zh(const float* __restrict__ gatew){
  int b=blockIdx.x, tid=threadIdx.x;
  __shared__ __align__(16) float zgr[DD], hlr[DD];
  zgr[tid]=g_zg[b*DD+tid]; hlr[tid]=g_hlocal[b*DD+tid];
  __syncthreads();
  const float* wt=gatew+tid;
  float acc=0.f;
  #pragma unroll 8
  for(int k=0;k<DD;k+=4){
    float4 z4=*(const float4*)&zgr[k];
    float4 l4=*(const float4*)&hlr[k];
    acc=fmaf(z4.x,wt[(k  )*DD],acc); acc=fmaf(l4.x,wt[(DD+k  )*DD],acc);
    acc=fmaf(z4.y,wt[(k+1)*DD],acc); acc=fmaf(l4.y,wt[(DD+k+1)*DD],acc);
    acc=fmaf(z4.z,wt[(k+2)*DD],acc); acc=fmaf(l4.z,wt[(DD+k+2)*DD],acc);
    acc=fmaf(z4.w,wt[(k+3)*DD],acc); acc=fmaf(l4.w,wt[(DD+k+3)*DD],acc);
  }
  float gf=sigm(acc)*0.1f;
  float zh=gf*hlr[tid]+(1.f-gf)*zgr[tid];
  g_zhT[tid*BB+b]=zh;
}

// ---------------- k_scores ----------------
__global__ void k_scores(const float* __restrict__ emb, float* __restrict__ out){
  int n0 = blockIdx.x*32; int tid=threadIdx.x;
  __shared__ __align__(16) float es[32][DD];
  int nmax = NSCORE - n0; if(nmax>32) nmax=32;
  for(int idx=tid; idx<nmax*DD; idx+=128){
    int nn=idx>>7, d=idx&127;
    es[nn][d]=emb[(long long)(n0+nn+1)*DD+d];
  }
  __syncthreads();
  float accv[32];
  #pragma unroll
  for(int nn=0;nn<32;nn++) accv[nn]=0.f;
  for(int d=0;d<DD;d+=4){
    float z0=g_zhT[(d  )*BB+tid];
    float z1=g_zhT[(d+1)*BB+tid];
    float z2=g_zhT[(d+2)*BB+tid];
    float z3=g_zhT[(d+3)*BB+tid];
    #pragma unroll
    for(int nn=0;nn<32;nn++){
      float4 e=*reinterpret_cast<const float4*>(&es[nn][d]);
      accv[nn]=fmaf(z0,e.x,fmaf(z1,e.y,fmaf(z2,e.z,fmaf(z3,e.w,accv[nn]))));
    }
  }
  for(int nn=0;nn<nmax;nn++)
    out[1 + (long long)tid*NSCORE + n0+nn] = accv[nn];
}

// ---------------- k_simi ----------------
__global__ void k_simi(const int* __restrict__ simi_mask){
  int blk=blockIdx.x; int b=blk/SS; int tid=threadIdx.x; // 64 threads
  __shared__ float f1[DD];
  __shared__ float sims[SS];
  f1[tid]   =g_hf1[blk*DD+tid];
  f1[tid+64]=g_hf1[blk*DD+tid+64];
  __syncthreads();
  if(tid<SS){
    const float* f2=&g_hf2[(b*SS+tid)*DD];
    float acc=0.f;
    for(int d=0;d<DD;d++) acc+=f1[d]*f2[d];
    sims[tid]=acc*2.0f;   // 1/TEMP
  }
  __syncthreads();
  if(tid==0){
    float m=-1e30f;
    for(int j=0;j<SS;j++) m=fmaxf(m,sims[j]);
    float den=0.f;
    for(int j=0;j<SS;j++) den+=expf(sims[j]-m);
    float loss=0.f;
    for(int j=0;j<SS;j++){
      float p=expf(sims[j]-m)/den;
      float l=-logf(p+1e-8f);
      if(simi_mask[blk*SS+j]==1) loss+=l;
    }
    g_partial[blk]=loss;
  }
}

__global__ void k_simi_final(float* __restrict__ out){
  int tid=threadIdx.x; // 128
  __shared__ float red[128];
  float a=0.f;
  for(int i=tid;i<BB*SS;i+=128) a+=g_partial[i];
  red[tid]=a; __syncthreads();
  for(int off=64;off>0;off>>=1){ if(tid<off) red[tid]+=red[tid+off]; __syncthreads(); }
  if(tid==0) out[0]=red[0]/(float)BB;
}

// ---------------- launch ----------------
extern "C" void kernel_launch(void* const* d_in, const int* in_sizes, int n_in,
                              void* d_out, int out_size){
  const int*   inputs =(const int*)  d_in[0];
  const int*   adj    =(const int*)  d_in[1];
  const int*   item   =(const int*)  d_in[2];
  const int*   simi   =(const int*)  d_in[3];
  const int*   as0    =(const int*)  d_in[4];
  const int*   as1    =(const int*)  d_in[5];
  const int*   ssl0   =(const int*)  d_in[6];
  const int*   ssl1   =(const int*)  d_in[7];
  // d_in[8] = last_item_mask (statically [:, -1]; unused)
  const int*   adj_all=(const int*)  d_in[9];
  const float* num    =(const float*)d_in[10];
  const float* emb    =(const float*)d_in[11];
  const float* pos    =(const float*)d_in[12];
  const float* a_local=(const float*)d_in[13];
  const float* mir1   =(const float*)d_in[14];
  const float* mir2   =(const float*)d_in[15];
  const float* gw1    =(const float*)d_in[16];
  const float* gw2    =(const float*)d_in[17];
  const float* gw3    =(const float*)d_in[18];
  const float* attr   =(const float*)d_in[19];
  const float* hww    =(const float*)d_in[20];
  const float* glu1   =(const float*)d_in[21];
  const float* glu2   =(const float*)d_in[22];
  const float* glu4   =(const float*)d_in[23];
  const float* glu4b  =(const float*)d_in[24];
  const float* ws     =(const float*)d_in[25];
  const float* gatew  =(const float*)d_in[26];
  float* out=(float*)d_out;

  float* p_out0;   cudaGetSymbolAddress((void**)&p_out0,  g_out0);
  float* p_out1;   cudaGetSymbolAddress((void**)&p_out1,  g_out1);
  float* p_hglob;  cudaGetSymbolAddress((void**)&p_hglob, g_hglob);
  float* p_logits; cudaGetSymbolAddress((void**)&p_logits,g_logits);

  k_pool<<<BB*SS,DD>>>(inputs, as0, as1, ssl0, ssl1, emb);
  k_attr<<<BB*SS,DD>>>(attr);
  k_sess<<<BB,DD>>>(inputs,item,emb);

  dim3 gSmall((600+63)/64, BB);   // 10 x 128
  dim3 gBig((7200+63)/64, BB);    // 113 x 128

  // mode 0: sv=emb[inputs], nv=emb children, hop-0 weights
  k_att_tc2<<<gSmall,128>>>(inputs,adj_all,num, emb, gw1, gw2, p_logits, 600, 0);
  k_soft_agg<<<BB*SS,32>>>(inputs,adj_all, emb, emb, p_logits, SS, 0);
  k_gemm3<<<BB*SS/32,128>>>(gw3, p_out0);

  // mode 1: neighbors-of-neighbors, hop-0 weights
  k_att_tc2<<<gBig,128>>>(inputs,adj_all,num, emb, gw1, gw2, p_logits, 7200, 1);
  k_soft_agg<<<BB*600,32>>>(inputs,adj_all, emb, emb, p_logits, 600, 1);
  k_gemm3<<<BB*600/32,128>>>(gw3, p_out1);

  // mode 2: sv=out0, nv=out1, hop-1 weights
  k_att_tc2<<<gSmall,128>>>(inputs,adj_all,num, p_out1, gw1+129*DD, gw2+DD, p_logits, 600, 2);
  k_soft_agg<<<BB*SS,32>>>(inputs,adj_all, p_out0, p_out1, p_logits, SS, 2);
  k_gemm3<<<BB*SS/32,128>>>(gw3+256*DD, p_hglob);

  // local branch: 2 iterations
  for(int it=0; it<2; it++){
    k_attx<<<BB,256>>>(adj, a_local + it*4*DD);
    k_gate<<<BB*SS,DD>>>(mir1 + it*DD*DD, mir2 + it*DD*DD);
  }
  k_highway<<<BB*SS,DD>>>(hww);
  k_hs<<<BB,DD>>>(inputs);
  k_c2<<<BB,DD>>>(glu2,glu4,glu4b);
  k_beta<<<BB*SS,DD>>>(inputs,pos,glu1,ws);
  k_zg<<<BB,DD>>>(pos);
  k_zh<<<BB,DD>>>(gatew);

  k_scores<<<(NSCORE+31)/32,128>>>(emb,out);
  k_simi<<<BB*SS,64>>>(simi);
  k_simi_final<<<1,128>>>(out);
}

// round 6
// speedup vs baseline: 1.0780x; 1.0780x over previous
#include <cuda_runtime.h>
#include <math.h>
#include <mma.h>
using namespace nvcuda;

#define BB 128
#define SS 50
#define DD 128
#define NNODE 40000
#define SAMP 12
#define NNEI 8
#define LEAKC 0.2f
#define NSCORE 39999

// ---------------- scratch (device globals; no allocation) ----------------
__device__ float g_h[BB*SS*DD];
__device__ float g_hf1[BB*SS*DD];
__device__ float g_hf2[BB*SS*DD];
__device__ float g_x[BB*SS*DD];
__device__ float g_mirror[BB*SS*DD];
__device__ float g_xnew[BB*SS*DD];
__device__ float g_xdot[BB*SS*DD];
__device__ float g_sess[BB*DD];
__device__ float g_out0[BB*SS*DD];
__device__ float g_out1[BB*600*DD];
__device__ float g_hglob[BB*SS*DD];
__device__ float g_hs[BB*DD];
__device__ float g_hlocal[BB*DD];
__device__ float g_c2[BB*DD];
__device__ float g_beta[BB*SS];
__device__ float g_zg[BB*DD];
__device__ float g_zhT[DD*BB];
__device__ float g_partial[BB*SS];
__device__ float g_cat[BB*600*2*DD];    // [rows][256] concat buffer
__device__ float g_logits[BB*7200];     // per-sample attention logits (mode 1)

__device__ __forceinline__ float sigm(float x){ return 1.0f/(1.0f+expf(-x)); }

// ---------------- k_pool: h, hf1, hf2 ----------------
__global__ void k_pool(const int* __restrict__ inputs,
                       const int* __restrict__ as0, const int* __restrict__ as1,
                       const int* __restrict__ ssl0, const int* __restrict__ ssl1,
                       const float* __restrict__ emb){
  int blk = blockIdx.x; int tid = threadIdx.x;
  int node = inputs[blk];
  g_h[blk*DD+tid] = emb[node*DD+tid];
  float p1=0.f, p2=0.f;
  const int* L1[2] = {as0, as1};
  const int* L2[2] = {ssl0, ssl1};
  #pragma unroll
  for(int l=0;l<2;l++){
    float s=0.f,c=0.f;
    #pragma unroll
    for(int n=0;n<NNEI;n++){ int id=L1[l][blk*NNEI+n]; if(id!=0){ s+=emb[id*DD+tid]; c+=1.f; } }
    p1 += s/(c+1e-8f);
    s=0.f;c=0.f;
    #pragma unroll
    for(int n=0;n<NNEI;n++){ int id=L2[l][blk*NNEI+n]; if(id!=0){ s+=emb[id*DD+tid]; c+=1.f; } }
    p2 += s/(c+1e-8f);
  }
  g_hf1[blk*DD+tid] = p1*0.5f;
  g_hf2[blk*DD+tid] = p2*0.5f;
}

// ---------------- k_attr ----------------
__global__ void k_attr(const float* __restrict__ attr_w){
  int blk=blockIdx.x, tid=threadIdx.x;
  __shared__ __align__(16) float hr[DD], fr[DD];
  hr[tid]=g_h[blk*DD+tid]; fr[tid]=g_hf1[blk*DD+tid];
  __syncthreads();
  const float* wt = attr_w + tid;
  float acc=0.f;
  #pragma unroll 8
  for(int k=0;k<DD;k+=4){
    float4 h4=*(const float4*)&hr[k];
    acc=fmaf(h4.x,wt[(k  )*DD],acc); acc=fmaf(h4.y,wt[(k+1)*DD],acc);
    acc=fmaf(h4.z,wt[(k+2)*DD],acc); acc=fmaf(h4.w,wt[(k+3)*DD],acc);
  }
  #pragma unroll 8
  for(int k=0;k<DD;k+=4){
    float4 f4=*(const float4*)&fr[k];
    acc=fmaf(f4.x,wt[(DD+k  )*DD],acc); acc=fmaf(f4.y,wt[(DD+k+1)*DD],acc);
    acc=fmaf(f4.z,wt[(DD+k+2)*DD],acc); acc=fmaf(f4.w,wt[(DD+k+3)*DD],acc);
  }
  float g=sigm(acc);
  float hf = g*hr[tid] + (1.f-g)*fr[tid];
  g_x[blk*DD+tid]=hr[tid];
  g_mirror[blk*DD+tid]=hf;
}

// ---------------- k_sess ----------------
__global__ void k_sess(const int* __restrict__ inputs, const int* __restrict__ item,
                       const float* __restrict__ emb){
  int b=blockIdx.x, tid=threadIdx.x;
  float acc=0.f, cnt=0.f;
  for(int s=0;s<SS;s++){
    int inp=inputs[b*SS+s];
    if(inp!=0){ acc += emb[item[b*SS+s]*DD+tid]; cnt+=1.f; }
  }
  g_sess[b*DD+tid]=acc/cnt;
}

// ---------------- k_att: scalar attention (modes 0 & 2, fused; 32 thr, 4 cols/thr) ----------------
__global__ void __launch_bounds__(32) k_att(
                       const int* __restrict__ inputs, const int* __restrict__ adj_all,
                       const float* __restrict__ num, const float* __restrict__ emb,
                       const float* __restrict__ w1, const float* __restrict__ w2,
                       int N, int mode){
  int blk=blockIdx.x; int b=blk/N; int i=blk-b*N; int tid=threadIdx.x;
  int c0=tid, c1=tid+32, c2=tid+64, c3=tid+96;
  __shared__ __align__(16) float nv_s[SAMP][DD];
  __shared__ __align__(16) float sess_s[DD];
  __shared__ float nw_s[SAMP];
  __shared__ int   ci_s[SAMP];

  int node = inputs[b*SS+i];
  if(tid<SAMP){
    ci_s[tid] = adj_all[node*SAMP+tid];
    nw_s[tid] = num[node*SAMP+tid];
  }
  ((float4*)sess_s)[tid] = ((const float4*)&g_sess[b*DD])[tid];
  __syncwarp();
  float4 sv4;
  if(mode==2){
    sv4 = ((const float4*)&g_out0[(b*SS+i)*DD])[tid];
    #pragma unroll
    for(int s=0;s<SAMP;s++)
      ((float4*)nv_s[s])[tid] = ((const float4*)&g_out1[(b*600 + i*SAMP+s)*DD])[tid];
  } else {
    sv4 = ((const float4*)&emb[(long long)node*DD])[tid];
    #pragma unroll
    for(int s=0;s<SAMP;s++)
      ((float4*)nv_s[s])[tid] = ((const float4*)&emb[(long long)ci_s[s]*DD])[tid];
  }
  ((float4*)&g_cat[(long long)blk*2*DD])[tid] = sv4;
  __syncwarp();

  float acc0[SAMP], acc1[SAMP], acc2[SAMP], acc3[SAMP];
  {
    float wl0=w1[DD*DD+c0], wl1=w1[DD*DD+c1], wl2=w1[DD*DD+c2], wl3=w1[DD*DD+c3];
    #pragma unroll
    for(int s=0;s<SAMP;s++){
      float nw=nw_s[s];
      acc0[s]=nw*wl0; acc1[s]=nw*wl1; acc2[s]=nw*wl2; acc3[s]=nw*wl3;
    }
  }
  #pragma unroll 1
  for(int d=0;d<DD;d+=4){
    float4 se = *(const float4*)&sess_s[d];
    const float* wr = w1 + d*DD;
    float a00=se.x*wr[c0],      a01=se.x*wr[c1],      a02=se.x*wr[c2],      a03=se.x*wr[c3];
    float a10=se.y*wr[DD+c0],   a11=se.y*wr[DD+c1],   a12=se.y*wr[DD+c2],   a13=se.y*wr[DD+c3];
    float a20=se.z*wr[2*DD+c0], a21=se.z*wr[2*DD+c1], a22=se.z*wr[2*DD+c2], a23=se.z*wr[2*DD+c3];
    float a30=se.w*wr[3*DD+c0], a31=se.w*wr[3*DD+c1], a32=se.w*wr[3*DD+c2], a33=se.w*wr[3*DD+c3];
    #pragma unroll
    for(int s=0;s<SAMP;s++){
      float4 v = *(const float4*)&nv_s[s][d];
      acc0[s] = fmaf(v.x,a00, fmaf(v.y,a10, fmaf(v.z,a20, fmaf(v.w,a30, acc0[s]))));
      acc1[s] = fmaf(v.x,a01, fmaf(v.y,a11, fmaf(v.z,a21, fmaf(v.w,a31, acc1[s]))));
      acc2[s] = fmaf(v.x,a02, fmaf(v.y,a12, fmaf(v.z,a22, fmaf(v.w,a32, acc2[s]))));
      acc3[s] = fmaf(v.x,a03, fmaf(v.y,a13, fmaf(v.z,a23, fmaf(v.w,a33, acc3[s]))));
    }
  }
  float w20=w2[c0], w21=w2[c1], w22=w2[c2], w23=w2[c3];
  float lg[SAMP];
  #pragma unroll
  for(int s=0;s<SAMP;s++){
    float a=acc0[s]; a=(a>0.f)?a:(LEAKC*a);
    float bq=acc1[s]; bq=(bq>0.f)?bq:(LEAKC*bq);
    float cq=acc2[s]; cq=(cq>0.f)?cq:(LEAKC*cq);
    float dq=acc3[s]; dq=(dq>0.f)?dq:(LEAKC*dq);
    float p = a*w20 + bq*w21 + cq*w22 + dq*w23;
    p += __shfl_xor_sync(0xffffffffu, p, 16);
    p += __shfl_xor_sync(0xffffffffu, p, 8);
    p += __shfl_xor_sync(0xffffffffu, p, 4);
    p += __shfl_xor_sync(0xffffffffu, p, 2);
    p += __shfl_xor_sync(0xffffffffu, p, 1);
    lg[s]=p;
  }
  float m=-1e30f;
  #pragma unroll
  for(int s=0;s<SAMP;s++) m=fmaxf(m, lg[s]);
  float alpha[SAMP]; float den=0.f;
  #pragma unroll
  for(int s=0;s<SAMP;s++){ alpha[s]=expf(lg[s]-m); den+=alpha[s]; }
  float inv=1.f/den;
  float g0=0.f,g1=0.f,g2=0.f,g3=0.f;
  #pragma unroll
  for(int s=0;s<SAMP;s++){
    float al=alpha[s];
    g0=fmaf(al,nv_s[s][c0],g0); g1=fmaf(al,nv_s[s][c1],g1);
    g2=fmaf(al,nv_s[s][c2],g2); g3=fmaf(al,nv_s[s][c3],g3);
  }
  float* crow = &g_cat[(long long)blk*2*DD + DD];
  crow[c0]=g0*inv; crow[c1]=g1*inv; crow[c2]=g2*inv; crow[c3]=g3*inv;
}

// ---------------- k_att_tc3: TF32 TC logits for mode 1. 512 thr, 256 rows/CTA ----------------
// logits[row] = sum_c leaky( (A@B)[row][c] + nw*w1_last[c] ) * w2[c]
// A[r][d] = emb[ci(r)][d],  B[d][c] = sess[b][d]*w1[d][c]
__global__ void __launch_bounds__(512) k_att_tc3(
    const int* __restrict__ inputs, const int* __restrict__ adj_all,
    const float* __restrict__ num, const float* __restrict__ emb,
    const float* __restrict__ w1, const float* __restrict__ w2,
    float* __restrict__ logits)
{
  const int ROWS = 256;
  const int LDA = 20;    // 16 k + 4 pad
  const int LDB = 132;
  const int rowsPerB = 7200;
  int b = blockIdx.y;
  int row0 = blockIdx.x*ROWS;
  int tid = threadIdx.x, warp = tid>>5, lane = tid&31;

  __shared__ float sess_s[DD];
  __shared__ float w1last_s[DD];
  __shared__ float w2_s[DD];
  __shared__ float nw_s[ROWS];
  __shared__ int   ci_s[ROWS];
  __shared__ __align__(16) float As[ROWS*LDA];   // 5120 floats (reused as epi buffers)
  __shared__ __align__(16) float Bs[16*LDB];     // 2112 floats

  if(tid<DD){
    sess_s[tid]   = g_sess[b*DD+tid];
    w1last_s[tid] = w1[DD*DD+tid];
    w2_s[tid]     = w2[tid];
  }
  if(tid<ROWS){
    int r = row0 + tid;
    int rr = (r < rowsPerB) ? r : 0;
    int gi = rr/SAMP, s = rr - gi*SAMP;
    int pi = gi/SAMP, ps = gi - pi*SAMP;
    int node = adj_all[inputs[b*SS+pi]*SAMP+ps];
    ci_s[tid] = adj_all[node*SAMP+s];
    nw_s[tid] = num[node*SAMP+s];
  }
  __syncthreads();

  wmma::fragment<wmma::accumulator,16,16,8,float> acc[8];
  #pragma unroll
  for(int n=0;n<8;n++) wmma::fill_fragment(acc[n], 0.0f);

  int rA = tid>>1, halfA = tid&1;      // A staging: 2 thr/row, 8 floats each
  int kkB = tid>>5, jB = tid&31;       // B staging: 16 rows x 32 thr (1 float4)

  for(int k0=0;k0<DD;k0+=16){
    {
      const float* ap = emb + (long long)ci_s[rA]*DD + k0 + halfA*8;
      float* as = As + rA*LDA + halfA*8;
      float4 v0 = *(const float4*)&ap[0];
      float4 v1 = *(const float4*)&ap[4];
      v0.x=wmma::__float_to_tf32(v0.x); v0.y=wmma::__float_to_tf32(v0.y);
      v0.z=wmma::__float_to_tf32(v0.z); v0.w=wmma::__float_to_tf32(v0.w);
      v1.x=wmma::__float_to_tf32(v1.x); v1.y=wmma::__float_to_tf32(v1.y);
      v1.z=wmma::__float_to_tf32(v1.z); v1.w=wmma::__float_to_tf32(v1.w);
      *(float4*)&as[0]=v0; *(float4*)&as[4]=v1;
    }
    {
      float sv = sess_s[k0+kkB];
      const float* bp = w1 + (long long)(k0+kkB)*DD + jB*4;
      float4 v = *(const float4*)bp;
      v.x=wmma::__float_to_tf32(v.x*sv); v.y=wmma::__float_to_tf32(v.y*sv);
      v.z=wmma::__float_to_tf32(v.z*sv); v.w=wmma::__float_to_tf32(v.w*sv);
      *(float4*)&Bs[kkB*LDB + jB*4]=v;
    }
    __syncthreads();
    #pragma unroll
    for(int kk0=0;kk0<16;kk0+=8){
      wmma::fragment<wmma::matrix_a,16,16,8,wmma::precision::tf32,wmma::row_major> afrag;
      wmma::load_matrix_sync(afrag, As + (warp*16)*LDA + kk0, LDA);
      #pragma unroll
      for(int n=0;n<8;n++){
        wmma::fragment<wmma::matrix_b,16,16,8,wmma::precision::tf32,wmma::row_major> bfrag;
        wmma::load_matrix_sync(bfrag, Bs + kk0*LDB + n*16, LDB);
        wmma::mma_sync(acc[n], afrag, bfrag, acc[n]);
      }
    }
    __syncthreads();
  }

  // epilogue: per-warp 16x20 tile buffer in the As region (16 warps x 320 = 5120)
  float* epi = As + warp*320;
  int r2 = lane>>1, half = lane&1;
  float nw = nw_s[warp*16 + r2];
  float v = 0.f;
  #pragma unroll
  for(int n=0;n<8;n++){
    wmma::store_matrix_sync(epi, acc[n], 20, wmma::mem_row_major);
    __syncwarp();
    const float* crow = epi + r2*20 + half*8;
    int cb = n*16 + half*8;
    #pragma unroll
    for(int j=0;j<8;j++){
      float t = crow[j] + nw*w1last_s[cb+j];
      t = (t>0.f)?t:(LEAKC*t);
      v = fmaf(t, w2_s[cb+j], v);
    }
    __syncwarp();
  }
  v += __shfl_xor_sync(0xffffffffu, v, 1);
  int rg = row0 + warp*16 + r2;
  if(half==0 && rg<rowsPerB) logits[(long long)b*rowsPerB + rg] = v;
}

// ---------------- k_soft_agg: softmax over 12 logits, agg, write cat row (mode 1) ----------------
__global__ void __launch_bounds__(32) k_soft_agg(
    const int* __restrict__ inputs, const int* __restrict__ adj_all,
    const float* __restrict__ emb, const float* __restrict__ logits)
{
  const int N = 600;
  int blk=blockIdx.x; int b=blk/N; int i=blk-b*N; int tid=threadIdx.x;
  __shared__ int   ci_s[SAMP];
  __shared__ float lg_s[SAMP];
  int pi=i/SAMP, ps=i-pi*SAMP;
  int node = adj_all[inputs[b*SS+pi]*SAMP+ps];
  if(tid<SAMP){
    ci_s[tid] = adj_all[node*SAMP+tid];
    lg_s[tid] = logits[(long long)b*7200 + i*SAMP + tid];
  }
  __syncwarp();
  float lg[SAMP];
  #pragma unroll
  for(int s=0;s<SAMP;s++) lg[s]=lg_s[s];
  float m=-1e30f;
  #pragma unroll
  for(int s=0;s<SAMP;s++) m=fmaxf(m,lg[s]);
  float alpha[SAMP]; float den=0.f;
  #pragma unroll
  for(int s=0;s<SAMP;s++){ alpha[s]=expf(lg[s]-m); den+=alpha[s]; }
  float inv=1.f/den;
  float4 sv4 = ((const float4*)&emb[(long long)node*DD])[tid];
  float a0=0.f,a1=0.f,a2=0.f,a3=0.f;
  #pragma unroll
  for(int s=0;s<SAMP;s++){
    float4 nv4 = ((const float4*)&emb[(long long)ci_s[s]*DD])[tid];
    float al = alpha[s];
    a0=fmaf(al,nv4.x,a0); a1=fmaf(al,nv4.y,a1); a2=fmaf(al,nv4.z,a2); a3=fmaf(al,nv4.w,a3);
  }
  float* crow = &g_cat[(long long)blk*2*DD];
  ((float4*)crow)[tid] = sv4;
  float4 ag; ag.x=a0*inv; ag.y=a1*inv; ag.z=a2*inv; ag.w=a3*inv;
  ((float4*)(crow+DD))[tid] = ag;
}

// ---------------- k_gemm3: out = tanh(cat @ W3), tiled 32 rows x 128 cols ----------------
__global__ void __launch_bounds__(128) k_gemm3(const float* __restrict__ w3,
                                               float* __restrict__ out){
  int row0 = blockIdx.x*32; int tid=threadIdx.x;
  int c = tid;
  __shared__ __align__(16) float As[16][32];
  float acc[32];
  #pragma unroll
  for(int r=0;r<32;r++) acc[r]=0.f;
  int rld = tid & 31;
  int kq  = tid >> 5;
  for(int k0=0;k0<2*DD;k0+=16){
    float4 av = *(const float4*)&g_cat[(long long)(row0+rld)*2*DD + k0 + kq*4];
    As[kq*4+0][rld]=av.x; As[kq*4+1][rld]=av.y; As[kq*4+2][rld]=av.z; As[kq*4+3][rld]=av.w;
    __syncthreads();
    const float* w3c = w3 + (long long)k0*DD + c;
    #pragma unroll 4
    for(int k=0;k<16;k++){
      float bk = w3c[k*DD];
      #pragma unroll
      for(int r4=0;r4<8;r4++){
        float4 a = *(const float4*)&As[k][r4*4];
        acc[r4*4+0]=fmaf(a.x,bk,acc[r4*4+0]);
        acc[r4*4+1]=fmaf(a.y,bk,acc[r4*4+1]);
        acc[r4*4+2]=fmaf(a.z,bk,acc[r4*4+2]);
        acc[r4*4+3]=fmaf(a.w,bk,acc[r4*4+3]);
      }
    }
    __syncthreads();
  }
  #pragma unroll
  for(int r=0;r<32;r++)
    out[(long long)(row0+r)*DD + c] = tanhf(acc[r]);
}

// ---------------- k_attx ----------------
__global__ void k_attx(const int* __restrict__ adj, const float* __restrict__ a_local){
  int b=blockIdx.x; int tid=threadIdx.x;  // 256 threads
  __shared__ __align__(16) float xs[SS][DD+4];
  __shared__ __align__(16) float al_s[4][DD];
  __shared__ float att[SS][SS+2];
  for(int idx=tid; idx<SS*DD; idx+=256){
    int i=idx>>7, d=idx&127;
    xs[i][d]=g_x[(b*SS+i)*DD+d];
  }
  for(int idx=tid; idx<4*DD; idx+=256)
    al_s[idx>>7][idx&127]=a_local[idx];
  __syncthreads();
  for(int p=tid;p<SS*SS;p+=256){
    int i=p/SS, j=p-i*SS;
    int k=adj[b*SS*SS+p];
    float e=-9e15f;
    if(k>=1 && k<=4){
      const float* al = al_s[k-1];
      float ds=0.f;
      #pragma unroll 8
      for(int d=0;d<DD;d+=4){
        float4 xi=*(const float4*)&xs[i][d];
        float4 xj=*(const float4*)&xs[j][d];
        float4 av=*(const float4*)&al[d];
        ds += xi.x*xj.x*av.x + xi.y*xj.y*av.y + xi.z*xj.z*av.z + xi.w*xj.w*av.w;
      }
      e = (ds>0.f)?ds:(LEAKC*ds);
    }
    att[i][j]=e;
  }
  __syncthreads();
  if(tid<SS){
    float m=-1e30f;
    for(int j=0;j<SS;j++) m=fmaxf(m,att[tid][j]);
    float den=0.f;
    for(int j=0;j<SS;j++){ float e=expf(att[tid][j]-m); att[tid][j]=e; den+=e; }
    float inv=1.f/den;
    for(int j=0;j<SS;j++) att[tid][j]*=inv;
  }
  __syncthreads();
  for(int q=tid;q<SS*DD;q+=256){
    int i=q>>7, d=q&127;
    float acc=0.f;
    for(int j=0;j<SS;j++) acc += att[i][j]*xs[j][d];
    g_xnew[(b*SS+i)*DD+d]=acc;
  }
}

// ---------------- k_gate ----------------
__global__ void k_gate(const float* __restrict__ w1, const float* __restrict__ w2){
  int blk=blockIdx.x, tid=threadIdx.x;
  __shared__ __align__(16) float xn[DD], mr[DD];
  xn[tid]=g_xnew[blk*DD+tid]; mr[tid]=g_mirror[blk*DD+tid];
  __syncthreads();
  const float* w1t=w1+tid; const float* w2t=w2+tid;
  float acc=0.f;
  #pragma unroll 8
  for(int k=0;k<DD;k+=4){
    float4 x4=*(const float4*)&xn[k];
    float4 m4=*(const float4*)&mr[k];
    acc=fmaf(x4.x,w1t[(k  )*DD],acc); acc=fmaf(m4.x,w2t[(k  )*DD],acc);
    acc=fmaf(x4.y,w1t[(k+1)*DD],acc); acc=fmaf(m4.y,w2t[(k+1)*DD],acc);
    acc=fmaf(x4.z,w1t[(k+2)*DD],acc); acc=fmaf(m4.z,w2t[(k+2)*DD],acc);
    acc=fmaf(x4.w,w1t[(k+3)*DD],acc); acc=fmaf(m4.w,w2t[(k+3)*DD],acc);
  }
  float gm=sigm(acc);
  float xv=xn[tid], mv=mr[tid];
  g_x[blk*DD+tid]     = gm*xv + (1.f-gm)*mv;
  g_mirror[blk*DD+tid]= gm*mv + (1.f-gm)*xv;
}

// ---------------- k_highway ----------------
__global__ void k_highway(const float* __restrict__ hw){
  int blk=blockIdx.x, tid=threadIdx.x;
  __shared__ __align__(16) float hr[DD], xr[DD];
  hr[tid]=g_h[blk*DD+tid]; xr[tid]=g_x[blk*DD+tid];
  __syncthreads();
  const float* wt=hw+tid;
  float acc=0.f;
  #pragma unroll 8
  for(int k=0;k<DD;k+=4){
    float4 h4=*(const float4*)&hr[k];
    float4 x4=*(const float4*)&xr[k];
    acc=fmaf(h4.x,wt[(k  )*DD],acc); acc=fmaf(x4.x,wt[(DD+k  )*DD],acc);
    acc=fmaf(h4.y,wt[(k+1)*DD],acc); acc=fmaf(x4.y,wt[(DD+k+1)*DD],acc);
    acc=fmaf(h4.z,wt[(k+2)*DD],acc); acc=fmaf(x4.z,wt[(DD+k+2)*DD],acc);
    acc=fmaf(h4.w,wt[(k+3)*DD],acc); acc=fmaf(x4.w,wt[(DD+k+3)*DD],acc);
  }
  float g=sigm(acc);
  float xd=g*hr[tid]+(1.f-g)*xr[tid];
  g_xdot[blk*DD+tid]=xd;
  int s=blk%SS;
  if(s==SS-1) g_hlocal[(blk/SS)*DD+tid]=xd;
}

// ---------------- k_hs ----------------
__global__ void k_hs(const int* __restrict__ inputs){
  int b=blockIdx.x, tid=threadIdx.x;
  float acc=0.f, cnt=0.f;
  for(int s=0;s<SS;s++){
    if(inputs[b*SS+s]!=0){ acc += g_hglob[(b*SS+s)*DD+tid]; cnt+=1.f; }
  }
  g_hs[b*DD+tid]=acc/cnt;
}

// ---------------- k_c2 ----------------
__global__ void k_c2(const float* __restrict__ glu2, const float* __restrict__ glu4,
                     const float* __restrict__ glu4b){
  int b=blockIdx.x, tid=threadIdx.x;
  __shared__ __align__(16) float hsr[DD], hlr[DD];
  hsr[tid]=g_hs[b*DD+tid]; hlr[tid]=g_hlocal[b*DD+tid];
  __syncthreads();
  float acc=glu4b[tid];
  const float* w2t=glu2+tid; const float* w4t=glu4+tid;
  #pragma unroll 8
  for(int k=0;k<DD;k+=4){
    float4 s4=*(const float4*)&hsr[k];
    float4 l4=*(const float4*)&hlr[k];
    acc=fmaf(s4.x,w2t[(k  )*DD],acc); acc=fmaf(l4.x,w4t[(k  )*DD],acc);
    acc=fmaf(s4.y,w2t[(k+1)*DD],acc); acc=fmaf(l4.y,w4t[(k+1)*DD],acc);
    acc=fmaf(s4.z,w2t[(k+2)*DD],acc); acc=fmaf(l4.z,w4t[(k+2)*DD],acc);
    acc=fmaf(s4.w,w2t[(k+3)*DD],acc); acc=fmaf(l4.w,w4t[(k+3)*DD],acc);
  }
  g_c2[b*DD+tid]=acc;
}

// ---------------- k_beta ----------------
__global__ void k_beta(const int* __restrict__ inputs, const float* __restrict__ pos,
                       const float* __restrict__ glu1, const float* __restrict__ ws){
  int blk=blockIdx.x, tid=threadIdx.x;
  int s=blk%SS, b=blk/SS;
  __shared__ __align__(16) float hp[DD];
  __shared__ float red[DD];
  hp[tid]=g_xdot[blk*DD+tid] + pos[s*DD+tid];
  __syncthreads();
  const float* wt=glu1+tid;
  float acc=0.f;
  #pragma unroll 8
  for(int k=0;k<DD;k+=4){
    float4 h4=*(const float4*)&hp[k];
    acc=fmaf(h4.x,wt[(k  )*DD],acc); acc=fmaf(h4.y,wt[(k+1)*DD],acc);
    acc=fmaf(h4.z,wt[(k+2)*DD],acc); acc=fmaf(h4.w,wt[(k+3)*DD],acc);
  }
  float nh=sigm(acc + g_c2[b*DD+tid]);
  red[tid]=nh*ws[tid];
  __syncthreads();
  for(int off=64;off>0;off>>=1){ if(tid<off) red[tid]+=red[tid+off]; __syncthreads(); }
  if(tid==0){
    float mi=(inputs[blk]!=0)?1.f:0.f;
    g_beta[blk]=red[0]*mi;
  }
}

// ---------------- k_zg ----------------
__global__ void k_zg(const float* __restrict__ pos){
  int b=blockIdx.x, tid=threadIdx.x;
  float acc=0.f;
  for(int s=0;s<SS;s++)
    acc += g_beta[b*SS+s]*(g_xdot[(b*SS+s)*DD+tid]+pos[s*DD+tid]);
  g_zg[b*DD+tid]=acc;
}

// ---------------- k_zh ----------------
__global__ void k_zh(const float* __restrict__ gatew){
  int b=blockIdx.x, tid=threadIdx.x;
  __shared__ __align__(16) float zgr[DD], hlr[DD];
  zgr[tid]=g_zg[b*DD+tid]; hlr[tid]=g_hlocal[b*DD+tid];
  __syncthreads();
  const float* wt=gatew+tid;
  float acc=0.f;
  #pragma unroll 8
  for(int k=0;k<DD;k+=4){
    float4 z4=*(const float4*)&zgr[k];
    float4 l4=*(const float4*)&hlr[k];
    acc=fmaf(z4.x,wt[(k  )*DD],acc); acc=fmaf(l4.x,wt[(DD+k  )*DD],acc);
    acc=fmaf(z4.y,wt[(k+1)*DD],acc); acc=fmaf(l4.y,wt[(DD+k+1)*DD],acc);
    acc=fmaf(z4.z,wt[(k+2)*DD],acc); acc=fmaf(l4.z,wt[(DD+k+2)*DD],acc);
    acc=fmaf(z4.w,wt[(k+3)*DD],acc); acc=fmaf(l4.w,wt[(DD+k+3)*DD],acc);
  }
  float gf=sigm(acc)*0.1f;
  float zh=gf*hlr[tid]+(1.f-gf)*zgr[tid];
  g_zhT[tid*BB+b]=zh;
}

// ---------------- k_scores ----------------
__global__ void k_scores(const float* __restrict__ emb, float* __restrict__ out){
  int n0 = blockIdx.x*32; int tid=threadIdx.x;
  __shared__ __align__(16) float es[32][DD];
  int nmax = NSCORE - n0; if(nmax>32) nmax=32;
  for(int idx=tid; idx<nmax*DD; idx+=128){
    int nn=idx>>7, d=idx&127;
    es[nn][d]=emb[(long long)(n0+nn+1)*DD+d];
  }
  __syncthreads();
  float accv[32];
  #pragma unroll
  for(int nn=0;nn<32;nn++) accv[nn]=0.f;
  for(int d=0;d<DD;d+=4){
    float z0=g_zhT[(d  )*BB+tid];
    float z1=g_zhT[(d+1)*BB+tid];
    float z2=g_zhT[(d+2)*BB+tid];
    float z3=g_zhT[(d+3)*BB+tid];
    #pragma unroll
    for(int nn=0;nn<32;nn++){
      float4 e=*reinterpret_cast<const float4*>(&es[nn][d]);
      accv[nn]=fmaf(z0,e.x,fmaf(z1,e.y,fmaf(z2,e.z,fmaf(z3,e.w,accv[nn]))));
    }
  }
  for(int nn=0;nn<nmax;nn++)
    out[1 + (long long)tid*NSCORE + n0+nn] = accv[nn];
}

// ---------------- k_simi ----------------
__global__ void k_simi(const int* __restrict__ simi_mask){
  int blk=blockIdx.x; int b=blk/SS; int tid=threadIdx.x; // 64 threads
  __shared__ float f1[DD];
  __shared__ float sims[SS];
  f1[tid]   =g_hf1[blk*DD+tid];
  f1[tid+64]=g_hf1[blk*DD+tid+64];
  __syncthreads();
  if(tid<SS){
    const float* f2=&g_hf2[(b*SS+tid)*DD];
    float acc=0.f;
    for(int d=0;d<DD;d++) acc+=f1[d]*f2[d];
    sims[tid]=acc*2.0f;   // 1/TEMP
  }
  __syncthreads();
  if(tid==0){
    float m=-1e30f;
    for(int j=0;j<SS;j++) m=fmaxf(m,sims[j]);
    float den=0.f;
    for(int j=0;j<SS;j++) den+=expf(sims[j]-m);
    float loss=0.f;
    for(int j=0;j<SS;j++){
      float p=expf(sims[j]-m)/den;
      float l=-logf(p+1e-8f);
      if(simi_mask[blk*SS+j]==1) loss+=l;
    }
    g_partial[blk]=loss;
  }
}

__global__ void k_simi_final(float* __restrict__ out){
  int tid=threadIdx.x; // 128
  __shared__ float red[128];
  float a=0.f;
  for(int i=tid;i<BB*SS;i+=128) a+=g_partial[i];
  red[tid]=a; __syncthreads();
  for(int off=64;off>0;off>>=1){ if(tid<off) red[tid]+=red[tid+off]; __syncthreads(); }
  if(tid==0) out[0]=red[0]/(float)BB;
}

// ---------------- launch ----------------
extern "C" void kernel_launch(void* const* d_in, const int* in_sizes, int n_in,
                              void* d_out, int out_size){
  const int*   inputs =(const int*)  d_in[0];
  const int*   adj    =(const int*)  d_in[1];
  const int*   item   =(const int*)  d_in[2];
  const int*   simi   =(const int*)  d_in[3];
  const int*   as0    =(const int*)  d_in[4];
  const int*   as1    =(const int*)  d_in[5];
  const int*   ssl0   =(const int*)  d_in[6];
  const int*   ssl1   =(const int*)  d_in[7];
  // d_in[8] = last_item_mask (statically [:, -1]; unused)
  const int*   adj_all=(const int*)  d_in[9];
  const float* num    =(const float*)d_in[10];
  const float* emb    =(const float*)d_in[11];
  const float* pos    =(const float*)d_in[12];
  const float* a_local=(const float*)d_in[13];
  const float* mir1   =(const float*)d_in[14];
  const float* mir2   =(const float*)d_in[15];
  const float* gw1    =(const float*)d_in[16];
  const float* gw2    =(const float*)d_in[17];
  const float* gw3    =(const float*)d_in[18];
  const float* attr   =(const float*)d_in[19];
  const float* hww    =(const float*)d_in[20];
  const float* glu1   =(const float*)d_in[21];
  const float* glu2   =(const float*)d_in[22];
  const float* glu4   =(const float*)d_in[23];
  const float* glu4b  =(const float*)d_in[24];
  const float* ws     =(const float*)d_in[25];
  const float* gatew  =(const float*)d_in[26];
  float* out=(float*)d_out;

  float* p_out0;   cudaGetSymbolAddress((void**)&p_out0,  g_out0);
  float* p_out1;   cudaGetSymbolAddress((void**)&p_out1,  g_out1);
  float* p_hglob;  cudaGetSymbolAddress((void**)&p_hglob, g_hglob);
  float* p_logits; cudaGetSymbolAddress((void**)&p_logits,g_logits);

  k_pool<<<BB*SS,DD>>>(inputs, as0, as1, ssl0, ssl1, emb);
  k_attr<<<BB*SS,DD>>>(attr);
  k_sess<<<BB,DD>>>(inputs,item,emb);

  // mode 0: scalar fused path
  k_att<<<BB*SS,32>>>(inputs,adj_all,num, emb, gw1, gw2, SS, 0);
  k_gemm3<<<BB*SS/32,128>>>(gw3, p_out0);

  // mode 1: tensor-core logits + soft-agg + gemm3
  {
    dim3 g((7200+255)/256, BB);   // 29 x 128
    k_att_tc3<<<g,512>>>(inputs,adj_all,num, emb, gw1, gw2, p_logits);
  }
  k_soft_agg<<<BB*600,32>>>(inputs,adj_all, emb, p_logits);
  k_gemm3<<<BB*600/32,128>>>(gw3, p_out1);

  // mode 2: scalar fused path (hop-1 weights)
  k_att<<<BB*SS,32>>>(inputs,adj_all,num, emb, gw1+129*DD, gw2+DD, SS, 2);
  k_gemm3<<<BB*SS/32,128>>>(gw3+256*DD, p_hglob);

  // local branch: 2 iterations
  for(int it=0; it<2; it++){
    k_attx<<<BB,256>>>(adj, a_local + it*4*DD);
    k_gate<<<BB*SS,DD>>>(mir1 + it*DD*DD, mir2 + it*DD*DD);
  }
  k_highway<<<BB*SS,DD>>>(hww);
  k_hs<<<BB,DD>>>(inputs);
  k_c2<<<BB,DD>>>(glu2,glu4,glu4b);
  k_beta<<<BB*SS,DD>>>(inputs,pos,glu1,ws);
  k_zg<<<BB,DD>>>(pos);
  k_zh<<<BB,DD>>>(gatew);

  k_scores<<<(NSCORE+31)/32,128>>>(emb,out);
  k_simi<<<BB*SS,64>>>(simi);
  k_simi_final<<<1,128>>>(out);
}